// round 7
// baseline (speedup 1.0000x reference)
#include <cuda_runtime.h>
#include <math.h>

#define NN 10000
#define NSLICE 28
#define NCHUNK 5
#define NB 140                 // all co-resident (<=148 SMs)
#define NT 1024
#define OUTB 2048              // outputs per chunk (2 per thread)
#define MAXR 121               // max table rows any block needs
#define TW2 200                // u16 row width (even)
#define AWORDS (MAXR * 100)    // u32 words per table copy = 12100
#define DB (AWORDS * 4)        // byte offset of copy B = 48400
#define SLIST_OFF (2 * DB)     // 96800, 16B aligned
#define SLIST_MAX 512
#define SMEM_BYTES (SLIST_OFF + SLIST_MAX * 4)
#define NSEG 313
#define CPB 100                // compaction block (no A-row duty)
#define QSCALE 448.0f

__device__ float g_A[NN];                // A[di*100+j1] = sum_j2 sqrt(di^2+(j1-j2)^2)
__device__ int   g_list[NN];             // (i2+99)*200 + (j2+99)
__device__ int   g_nlist;
__device__ float g_pT[NSLICE * 10240];
__device__ float g_pS[NSLICE * 10240];
__device__ float g_red[NCHUNK];
__device__ int   g_barA = 0, g_barB = 0, g_ctr2 = 0, g_done = 0;

__device__ __forceinline__ void grid_barrier(int* ctr) {
    __syncthreads();
    if (threadIdx.x == 0) {
        atomicAdd(ctr, 1);
        while (*(volatile int*)ctr != NB) __nanosleep(32);
    }
    __syncthreads();
}

__device__ __forceinline__ float sqrt_fast(float x) {
    float r; asm("sqrt.approx.f32 %0, %1;" : "=f"(r) : "f"(x)); return r;
}

__global__ __launch_bounds__(NT, 1) void k_fused(const float* __restrict__ prob,
                                                 const float* __restrict__ gt,
                                                 float* __restrict__ out) {
    extern __shared__ unsigned char smraw[];
    unsigned* wA = (unsigned*)smraw;                 // u16-pair words, copy A
    unsigned* wB = (unsigned*)(smraw + DB);          // shifted copy B
    int* slist = (int*)(smraw + SLIST_OFF);

    const int bid = blockIdx.x;
    const int tid = threadIdx.x;
    const int warp = tid >> 5, lane = tid & 31;

    const int chunk = bid / NSLICE;
    const int s = bid - chunk * NSLICE;
    const int o0 = chunk * OUTB;
    const int i1lo = o0 / 100;
    int i1hi = (o0 + OUTB - 1) / 100; if (i1hi > 99) i1hi = 99;
    const int rlo = 99 - i1hi;
    const int nrows = 100 + (i1hi - i1lo);
    const int nW = nrows * 100;                      // u32 words per copy

    // ---------------- Phase A ----------------
    float v[10];
    if (bid == CPB) {
        // prefetch all gt values (MLP=10); latency hides under table fill
        #pragma unroll
        for (int it = 0; it < 10; ++it) {
            int o = (it * 32 + warp) * 32 + lane;
            v[it] = (o < NN) ? gt[o] : 0.0f;
        }
    } else if (bid < 100) {
        // one A-row per block (full fp32 precision)
        int j1 = tid;
        if (j1 < 100) {
            float fd2 = (float)(bid * bid);
            float a = 0.f;
            #pragma unroll 4
            for (int j2 = 0; j2 < 100; ++j2) {
                float dj = (float)(j1 - j2);
                a += sqrtf(fd2 + dj * dj);
            }
            g_A[bid * 100 + j1] = a;
        }
    }

    // all blocks: copy A of quantized table (u16 pairs)
    for (int w = tid; w < nW; w += NT) {
        int r = w / 100;
        int cw = w - r * 100;
        int dx = r + rlo - 99;
        int c0 = 2 * cw - 99;            // dy of even col
        int d2a = dx * dx + c0 * c0;
        int d2b = dx * dx + (c0 + 1) * (c0 + 1);
        unsigned ua = __float2uint_rn(sqrt_fast((float)d2a) * QSCALE);
        unsigned ub = __float2uint_rn(sqrt_fast((float)d2b) * QSCALE);
        wA[w] = ua | (ub << 16);
    }
    __syncthreads();
    // copy B: B[k] = A[k+1]  (one-u16 shift, built from copy A)
    for (int w = tid; w < nW; w += NT) {
        unsigned a = wA[w];
        unsigned b = wA[(w + 1 < nW) ? (w + 1) : w];
        wB[w] = __byte_perm(a, b, 0x5432);
    }

    if (bid == CPB) {
        // deterministic parallel compaction of py = (gt >= 0.5), data in regs
        __shared__ unsigned sbal[320];
        __shared__ int soff[320];
        #pragma unroll
        for (int it = 0; it < 10; ++it) {
            int seg = it * 32 + warp;
            if (seg < NSEG) {
                int o = seg * 32 + lane;
                bool p = (o < NN) && (v[it] >= 0.5f);
                unsigned bal = __ballot_sync(0xffffffffu, p);
                if (lane == 0) sbal[seg] = bal;
            }
        }
        __syncthreads();
        if (warp == 0) {
            int base = 0;
            #pragma unroll
            for (int c = 0; c < 10; ++c) {
                int sg = c * 32 + lane;
                int cnt = (sg < NSEG) ? __popc(sbal[sg]) : 0;
                int incl = cnt;
                #pragma unroll
                for (int d = 1; d < 32; d <<= 1) {
                    int vv = __shfl_up_sync(0xffffffffu, incl, d);
                    if (lane >= d) incl += vv;
                }
                if (sg < NSEG) soff[sg] = base + incl - cnt;
                base += __shfl_sync(0xffffffffu, incl, 31);
            }
            if (lane == 0) g_nlist = base;
        }
        __syncthreads();
        #pragma unroll
        for (int it = 0; it < 10; ++it) {
            int seg = it * 32 + warp;
            if (seg < NSEG) {
                unsigned bal = sbal[seg];
                if ((bal >> lane) & 1u) {
                    int o = seg * 32 + lane;
                    int pre = __popc(bal & ((1u << lane) - 1u));
                    int i2 = o / 100, j2 = o - i2 * 100;
                    g_list[soff[seg] + pre] = (i2 + 99) * TW2 + (j2 + 99);
                }
            }
        }
    }

    __threadfence();
    grid_barrier(&g_barA);

    // ---------------- Phase B: main sparse accumulate ----------------
    int n = *(volatile int*)&g_nlist;
    int e0 = (s * n) / NSLICE;
    int e1 = ((s + 1) * n) / NSLICE;
    int cnt = e1 - e0;
    int badj = rlo * TW2 + 1;            // F = G - badj
    for (int k = tid; k < cnt; k += NT) {
        int F = g_list[e0 + k] - badj;
        int p = F & 1;
        slist[k] = 2 * (F - p) + p * DB;
    }
    __syncthreads();

    int oe = o0 + 2 * tid;               // even output; pair (oe, oe+1)
    bool valid = (oe < NN);
    int oc = valid ? oe : (NN - 2);
    int i1 = oc / 100;
    int j1 = oc - i1 * 100;              // even
    int qq = j1 >> 1;

    unsigned baseA;
    asm("{ .reg .u64 t; cvta.to.shared.u64 t, %1; cvt.u32.u64 %0, t; }"
        : "=r"(baseA) : "l"(smraw));
    unsigned tb = baseA - 400u * (unsigned)i1 - 4u * (unsigned)qq;

    unsigned aE0 = 0, aE1 = 0, aO0 = 0, aO1 = 0;
    int k = 0;
    int n8 = cnt & ~7;
    for (; k < n8; k += 8) {
        int4 ea = *(const int4*)(slist + k);
        int4 eb = *(const int4*)(slist + k + 4);
        unsigned w0, w1, w2, w3, w4, w5, w6, w7;
        asm("ld.shared.u32 %0,[%1];" : "=r"(w0) : "r"(tb + (unsigned)ea.x));
        asm("ld.shared.u32 %0,[%1];" : "=r"(w1) : "r"(tb + (unsigned)ea.y));
        asm("ld.shared.u32 %0,[%1];" : "=r"(w2) : "r"(tb + (unsigned)ea.z));
        asm("ld.shared.u32 %0,[%1];" : "=r"(w3) : "r"(tb + (unsigned)ea.w));
        asm("ld.shared.u32 %0,[%1];" : "=r"(w4) : "r"(tb + (unsigned)eb.x));
        asm("ld.shared.u32 %0,[%1];" : "=r"(w5) : "r"(tb + (unsigned)eb.y));
        asm("ld.shared.u32 %0,[%1];" : "=r"(w6) : "r"(tb + (unsigned)eb.z));
        asm("ld.shared.u32 %0,[%1];" : "=r"(w7) : "r"(tb + (unsigned)eb.w));
        aE0 = __dp2a_lo(w0, 0x0100u, aE0); aO0 = __dp2a_lo(w0, 0x0001u, aO0);
        aE1 = __dp2a_lo(w1, 0x0100u, aE1); aO1 = __dp2a_lo(w1, 0x0001u, aO1);
        aE0 = __dp2a_lo(w2, 0x0100u, aE0); aO0 = __dp2a_lo(w2, 0x0001u, aO0);
        aE1 = __dp2a_lo(w3, 0x0100u, aE1); aO1 = __dp2a_lo(w3, 0x0001u, aO1);
        aE0 = __dp2a_lo(w4, 0x0100u, aE0); aO0 = __dp2a_lo(w4, 0x0001u, aO0);
        aE1 = __dp2a_lo(w5, 0x0100u, aE1); aO1 = __dp2a_lo(w5, 0x0001u, aO1);
        aE0 = __dp2a_lo(w6, 0x0100u, aE0); aO0 = __dp2a_lo(w6, 0x0001u, aO0);
        aE1 = __dp2a_lo(w7, 0x0100u, aE1); aO1 = __dp2a_lo(w7, 0x0001u, aO1);
    }
    for (; k < cnt; ++k) {
        unsigned w0;
        asm("ld.shared.u32 %0,[%1];" : "=r"(w0) : "r"(tb + (unsigned)slist[k]));
        aE0 = __dp2a_lo(w0, 0x0100u, aE0);
        aO0 = __dp2a_lo(w0, 0x0001u, aO0);
    }
    float Te = __uint2float_rn(aE0 + aE1) * (1.0f / QSCALE);
    float To = __uint2float_rn(aO0 + aO1) * (1.0f / QSCALE);

    // slice partial of the (input-independent) rowsum S for both outputs
    int i2a = (100 * s) / NSLICE;
    int i2b = (100 * (s + 1)) / NSLICE;
    float sve = 0.f, svo = 0.f;
    const float2* A2 = (const float2*)g_A;
    for (int i2 = i2a; i2 < i2b; ++i2) {
        int di = i1 - i2; if (di < 0) di = -di;
        float2 vv = A2[di * 50 + qq];
        sve += vv.x; svo += vv.y;
    }

    if (valid) {
        *(float2*)&g_pT[s * 10240 + oe] = make_float2(Te, To);
        *(float2*)&g_pS[s * 10240 + oe] = make_float2(sve, svo);
    }
    __threadfence();
    grid_barrier(&g_barB);

    // ---------------- Phase C: reduce (blocks with s == 0) ----------------
    if (s == 0) {
        __shared__ float warpsum[32];
        float ls = 0.f;
        if (valid) {
            float Txe = 0.f, Txo = 0.f, Sxe = 0.f, Sxo = 0.f;
            int widx = (o0 >> 1) + tid;
            #pragma unroll
            for (int q2 = 0; q2 < NSLICE; ++q2) {
                float2 t2 = ((const float2*)(g_pT + q2 * 10240))[widx];
                float2 s2 = ((const float2*)(g_pS + q2 * 10240))[widx];
                Txe += t2.x; Txo += t2.y;
                Sxe += s2.x; Sxo += s2.y;
            }
            float2 pr = *(const float2*)&prob[oe];
            float pxe = (pr.x >= 0.5f) ? 1.0f : 0.0f;
            float pxo = (pr.y >= 0.5f) ? 1.0f : 0.0f;
            ls = fabsf(pxe * Sxe - Txe) + fabsf(pxo * Sxo - Txo);
        }
        #pragma unroll
        for (int off = 16; off; off >>= 1) ls += __shfl_down_sync(0xffffffffu, ls, off);
        if (lane == 0) warpsum[warp] = ls;
        __syncthreads();
        if (tid == 0) {
            float t = 0.f;
            #pragma unroll
            for (int w = 0; w < 32; ++w) t += warpsum[w];
            g_red[chunk] = t;
            __threadfence();
            int old = atomicAdd(&g_ctr2, 1);
            if (old == NCHUNK - 1) {
                float tt = 0.f;
                #pragma unroll
                for (int b = 0; b < NCHUNK; ++b) tt += g_red[b];
                out[0] = tt * (1.0f / ((float)NN * (float)NN));
            }
        }
        __syncthreads();
    }

    // ---------------- replay-safe counter reset ----------------
    __syncthreads();
    if (tid == 0) {
        int fin = atomicAdd(&g_done, 1);
        if (fin == NB - 1) {
            g_barA = 0; g_barB = 0; g_ctr2 = 0; g_done = 0;
            __threadfence();
        }
    }
}

extern "C" void kernel_launch(void* const* d_in, const int* in_sizes, int n_in,
                              void* d_out, int out_size) {
    const float* prob = (const float*)d_in[0];
    const float* gt   = (const float*)d_in[1];
    float* out = (float*)d_out;

    cudaFuncSetAttribute(k_fused, cudaFuncAttributeMaxDynamicSharedMemorySize, SMEM_BYTES);
    k_fused<<<NB, NT, SMEM_BYTES>>>(prob, gt, out);
}

// round 8
// speedup vs baseline: 1.0816x; 1.0816x over previous
#include <cuda_runtime.h>
#include <math.h>

#define NN 10000
#define NSLICE 28
#define NCHUNK 5
#define NB 140                 // all co-resident (<=148 SMs)
#define NT 1024
#define OUTB 2048              // outputs per chunk (2 per thread)
#define MAXR 121               // max table rows any block needs
#define TW2 200                // u16 row width (even)
#define TABW (199 * 100)       // u32 words per global table copy = 19900
#define AWORDS (MAXR * 100)    // u32 words per smem copy = 12100
#define DB (AWORDS * 4)        // byte offset of smem copy B = 48400
#define SLIST_OFF (2 * DB)     // 96800, 16B aligned
#define SLIST_MAX 512
#define SMEM_BYTES (SLIST_OFF + SLIST_MAX * 4)
#define NSEG 313
#define CPB 100                // compaction block (no A-row duty)
#define QSCALE 448.0f

__device__ unsigned g_tabA[TABW];        // quantized u16-pair table, copy A
__device__ unsigned g_tabB[TABW];        // one-u16-shifted copy B
__device__ float g_A[NN];                // A[di*100+j1] = sum_j2 sqrt(di^2+(j1-j2)^2)
__device__ int   g_list[NN];             // (i2+99)*200 + (j2+99)
__device__ int   g_nlist;
__device__ float g_pT[NSLICE * 10240];
__device__ float g_pS[NSLICE * 10240];
__device__ float g_red[NCHUNK];
__device__ int   g_barA = 0, g_barB = 0, g_ctr2 = 0, g_done = 0;

__device__ __forceinline__ void grid_barrier(int* ctr) {
    __syncthreads();
    if (threadIdx.x == 0) {
        atomicAdd(ctr, 1);
        while (*(volatile int*)ctr != NB) __nanosleep(32);
    }
    __syncthreads();
}

__device__ __forceinline__ float sqrt_fast(float x) {
    float r; asm("sqrt.approx.f32 %0, %1;" : "=f"(r) : "f"(x)); return r;
}

// quantized distance at flat u16 index t of the 199x200 table
__device__ __forceinline__ unsigned qdist(int t) {
    int a = t / TW2;
    int c = t - a * TW2;
    int dx = a - 99, dy = c - 99;
    return __float2uint_rn(sqrt_fast((float)(dx * dx + dy * dy)) * QSCALE);
}

__global__ __launch_bounds__(NT, 1) void k_fused(const float* __restrict__ prob,
                                                 const float* __restrict__ gt,
                                                 float* __restrict__ out) {
    extern __shared__ unsigned char smraw[];
    unsigned* wA = (unsigned*)smraw;                 // u16-pair words, copy A
    unsigned* wB = (unsigned*)(smraw + DB);          // shifted copy B
    int* slist = (int*)(smraw + SLIST_OFF);

    const int bid = blockIdx.x;
    const int tid = threadIdx.x;
    const int warp = tid >> 5, lane = tid & 31;

    const int chunk = bid / NSLICE;
    const int s = bid - chunk * NSLICE;
    const int o0 = chunk * OUTB;
    const int i1lo = o0 / 100;
    int i1hi = (o0 + OUTB - 1) / 100; if (i1hi > 99) i1hi = 99;
    const int rlo = 99 - i1hi;
    const int nrows = 100 + (i1hi - i1lo);
    const int nW = nrows * 100;                      // u32 words per smem copy

    // ---------------- Phase A0: global work, split across all blocks ------
    // 1) Global quantized tables: 2*19900 words over 143360 threads -> 1 iter.
    {
        int idx = bid * NT + tid;
        if (idx < 2 * TABW) {
            if (idx < TABW) {
                int t0 = 2 * idx;
                g_tabA[idx] = qdist(t0) | (qdist(t0 + 1) << 16);
            } else {
                int w = idx - TABW;
                int t0 = 2 * w + 1;
                int t1 = (t0 + 1 < 2 * TABW) ? (t0 + 1) : t0;
                g_tabB[w] = qdist(t0) | (qdist(t1) << 16);
            }
        }
    }

    // 2) A-rows via prefix identity: A[di][j1] = r[0] + P[j1] + P[99-j1]
    if (bid < 100) {
        __shared__ float sr[100];
        __shared__ float sp[100];
        if (tid < 100) {
            float fd2 = (float)(bid * bid);
            sr[tid] = sqrtf(fd2 + (float)(tid * tid));
        }
        __syncthreads();
        if (tid == 0) {
            float run = 0.f;
            sp[0] = 0.f;
            for (int d = 1; d < 100; ++d) { run += sr[d]; sp[d] = run; }
        }
        __syncthreads();
        if (tid < 100)
            g_A[bid * 100 + tid] = sr[0] + sp[tid] + sp[99 - tid];
    } else if (bid == CPB) {
        // 3) deterministic parallel compaction of py = (gt >= 0.5)
        __shared__ unsigned sbal[320];
        __shared__ int soff[320];
        #pragma unroll
        for (int it = 0; it < 10; ++it) {
            int seg = it * 32 + warp;
            if (seg < NSEG) {
                int o = seg * 32 + lane;
                bool p = (o < NN) && (gt[o] >= 0.5f);
                unsigned bal = __ballot_sync(0xffffffffu, p);
                if (lane == 0) sbal[seg] = bal;
            }
        }
        __syncthreads();
        if (warp == 0) {
            int base = 0;
            #pragma unroll
            for (int c = 0; c < 10; ++c) {
                int sg = c * 32 + lane;
                int cnt = (sg < NSEG) ? __popc(sbal[sg]) : 0;
                int incl = cnt;
                #pragma unroll
                for (int d = 1; d < 32; d <<= 1) {
                    int vv = __shfl_up_sync(0xffffffffu, incl, d);
                    if (lane >= d) incl += vv;
                }
                if (sg < NSEG) soff[sg] = base + incl - cnt;
                base += __shfl_sync(0xffffffffu, incl, 31);
            }
            if (lane == 0) g_nlist = base;
        }
        __syncthreads();
        #pragma unroll
        for (int it = 0; it < 10; ++it) {
            int seg = it * 32 + warp;
            if (seg < NSEG) {
                unsigned bal = sbal[seg];
                if ((bal >> lane) & 1u) {
                    int o = seg * 32 + lane;
                    int pre = __popc(bal & ((1u << lane) - 1u));
                    int i2 = o / 100, j2 = o - i2 * 100;
                    g_list[soff[seg] + pre] = (i2 + 99) * TW2 + (j2 + 99);
                }
            }
        }
    }

    __threadfence();
    grid_barrier(&g_barA);

    // ---------------- Phase A1: stage table window from L2 into smem ------
    {
        const int4* srcA = (const int4*)(g_tabA + rlo * 100);
        const int4* srcB = (const int4*)(g_tabB + rlo * 100);
        int4* dA = (int4*)wA;
        int4* dB = (int4*)wB;
        int nv = nW >> 2;                     // 12100/4 = 3025
        for (int k2 = tid; k2 < nv; k2 += NT) {
            dA[k2] = srcA[k2];
            dB[k2] = srcB[k2];
        }
    }

    // ---------------- Phase B: main sparse accumulate ----------------
    int n = *(volatile int*)&g_nlist;
    int e0 = (s * n) / NSLICE;
    int e1 = ((s + 1) * n) / NSLICE;
    int cnt = e1 - e0;
    int badj = rlo * TW2 + 1;            // F = G - badj
    for (int k = tid; k < cnt; k += NT) {
        int F = g_list[e0 + k] - badj;
        int p = F & 1;
        slist[k] = 2 * (F - p) + p * DB;
    }
    __syncthreads();

    int oe = o0 + 2 * tid;               // even output; pair (oe, oe+1)
    bool valid = (oe < NN);
    int oc = valid ? oe : (NN - 2);
    int i1 = oc / 100;
    int j1 = oc - i1 * 100;              // even
    int qq = j1 >> 1;

    unsigned baseA;
    asm("{ .reg .u64 t; cvta.to.shared.u64 t, %1; cvt.u32.u64 %0, t; }"
        : "=r"(baseA) : "l"(smraw));
    unsigned tb = baseA - 400u * (unsigned)i1 - 4u * (unsigned)qq;

    unsigned aE0 = 0, aE1 = 0, aO0 = 0, aO1 = 0;
    int k = 0;
    int n8 = cnt & ~7;
    for (; k < n8; k += 8) {
        int4 ea = *(const int4*)(slist + k);
        int4 eb = *(const int4*)(slist + k + 4);
        unsigned w0, w1, w2, w3, w4, w5, w6, w7;
        asm("ld.shared.u32 %0,[%1];" : "=r"(w0) : "r"(tb + (unsigned)ea.x));
        asm("ld.shared.u32 %0,[%1];" : "=r"(w1) : "r"(tb + (unsigned)ea.y));
        asm("ld.shared.u32 %0,[%1];" : "=r"(w2) : "r"(tb + (unsigned)ea.z));
        asm("ld.shared.u32 %0,[%1];" : "=r"(w3) : "r"(tb + (unsigned)ea.w));
        asm("ld.shared.u32 %0,[%1];" : "=r"(w4) : "r"(tb + (unsigned)eb.x));
        asm("ld.shared.u32 %0,[%1];" : "=r"(w5) : "r"(tb + (unsigned)eb.y));
        asm("ld.shared.u32 %0,[%1];" : "=r"(w6) : "r"(tb + (unsigned)eb.z));
        asm("ld.shared.u32 %0,[%1];" : "=r"(w7) : "r"(tb + (unsigned)eb.w));
        aE0 = __dp2a_lo(w0, 0x0100u, aE0); aO0 = __dp2a_lo(w0, 0x0001u, aO0);
        aE1 = __dp2a_lo(w1, 0x0100u, aE1); aO1 = __dp2a_lo(w1, 0x0001u, aO1);
        aE0 = __dp2a_lo(w2, 0x0100u, aE0); aO0 = __dp2a_lo(w2, 0x0001u, aO0);
        aE1 = __dp2a_lo(w3, 0x0100u, aE1); aO1 = __dp2a_lo(w3, 0x0001u, aO1);
        aE0 = __dp2a_lo(w4, 0x0100u, aE0); aO0 = __dp2a_lo(w4, 0x0001u, aO0);
        aE1 = __dp2a_lo(w5, 0x0100u, aE1); aO1 = __dp2a_lo(w5, 0x0001u, aO1);
        aE0 = __dp2a_lo(w6, 0x0100u, aE0); aO0 = __dp2a_lo(w6, 0x0001u, aO0);
        aE1 = __dp2a_lo(w7, 0x0100u, aE1); aO1 = __dp2a_lo(w7, 0x0001u, aO1);
    }
    for (; k < cnt; ++k) {
        unsigned w0;
        asm("ld.shared.u32 %0,[%1];" : "=r"(w0) : "r"(tb + (unsigned)slist[k]));
        aE0 = __dp2a_lo(w0, 0x0100u, aE0);
        aO0 = __dp2a_lo(w0, 0x0001u, aO0);
    }
    float Te = __uint2float_rn(aE0 + aE1) * (1.0f / QSCALE);
    float To = __uint2float_rn(aO0 + aO1) * (1.0f / QSCALE);

    // slice partial of the (input-independent) rowsum S for both outputs
    int i2a = (100 * s) / NSLICE;
    int i2b = (100 * (s + 1)) / NSLICE;
    float sve = 0.f, svo = 0.f;
    const float2* A2 = (const float2*)g_A;
    for (int i2 = i2a; i2 < i2b; ++i2) {
        int di = i1 - i2; if (di < 0) di = -di;
        float2 vv = A2[di * 50 + qq];
        sve += vv.x; svo += vv.y;
    }

    if (valid) {
        *(float2*)&g_pT[s * 10240 + oe] = make_float2(Te, To);
        *(float2*)&g_pS[s * 10240 + oe] = make_float2(sve, svo);
    }
    __threadfence();
    grid_barrier(&g_barB);

    // ---------------- Phase C: reduce (blocks with s == 0) ----------------
    if (s == 0) {
        __shared__ float warpsum[32];
        float ls = 0.f;
        if (valid) {
            float Txe = 0.f, Txo = 0.f, Sxe = 0.f, Sxo = 0.f;
            int widx = (o0 >> 1) + tid;
            #pragma unroll
            for (int q2 = 0; q2 < NSLICE; ++q2) {
                float2 t2 = ((const float2*)(g_pT + q2 * 10240))[widx];
                float2 s2 = ((const float2*)(g_pS + q2 * 10240))[widx];
                Txe += t2.x; Txo += t2.y;
                Sxe += s2.x; Sxo += s2.y;
            }
            float2 pr = *(const float2*)&prob[oe];
            float pxe = (pr.x >= 0.5f) ? 1.0f : 0.0f;
            float pxo = (pr.y >= 0.5f) ? 1.0f : 0.0f;
            ls = fabsf(pxe * Sxe - Txe) + fabsf(pxo * Sxo - Txo);
        }
        #pragma unroll
        for (int off = 16; off; off >>= 1) ls += __shfl_down_sync(0xffffffffu, ls, off);
        if (lane == 0) warpsum[warp] = ls;
        __syncthreads();
        if (tid == 0) {
            float t = 0.f;
            #pragma unroll
            for (int w = 0; w < 32; ++w) t += warpsum[w];
            g_red[chunk] = t;
            __threadfence();
            int old = atomicAdd(&g_ctr2, 1);
            if (old == NCHUNK - 1) {
                float tt = 0.f;
                #pragma unroll
                for (int b = 0; b < NCHUNK; ++b) tt += g_red[b];
                out[0] = tt * (1.0f / ((float)NN * (float)NN));
            }
        }
        __syncthreads();
    }

    // ---------------- replay-safe counter reset ----------------
    __syncthreads();
    if (tid == 0) {
        int fin = atomicAdd(&g_done, 1);
        if (fin == NB - 1) {
            g_barA = 0; g_barB = 0; g_ctr2 = 0; g_done = 0;
            __threadfence();
        }
    }
}

extern "C" void kernel_launch(void* const* d_in, const int* in_sizes, int n_in,
                              void* d_out, int out_size) {
    const float* prob = (const float*)d_in[0];
    const float* gt   = (const float*)d_in[1];
    float* out = (float*)d_out;

    cudaFuncSetAttribute(k_fused, cudaFuncAttributeMaxDynamicSharedMemorySize, SMEM_BYTES);
    k_fused<<<NB, NT, SMEM_BYTES>>>(prob, gt, out);
}

// round 9
// speedup vs baseline: 1.1173x; 1.0329x over previous
#include <cuda_runtime.h>
#include <math.h>

#define NN 10000
#define NSLICE 28
#define NCHUNK 5
#define NB 140                 // all co-resident (<=148 SMs)
#define NT 1024
#define OUTB 2048              // outputs per chunk (2 per thread)
#define MAXR 121               // max table rows any block needs
#define TW2 200                // u16 row width (even)
#define TABW (199 * 100)       // u32 words per global table copy = 19900
#define AWORDS (MAXR * 100)    // u32 words per smem copy = 12100
#define DB (AWORDS * 4)        // byte offset of smem copy B = 48400
#define SLIST_OFF (2 * DB)     // 96800, 16B aligned
#define SLIST_MAX 512
#define SMEM_BYTES (SLIST_OFF + SLIST_MAX * 4)
#define NSEG 313
#define CPB 100                // compaction block (no A-row duty)
#define QSCALE 448.0f
#define OPC 72                 // outputs per block in phase C (72*140 >= 10000)

__device__ unsigned g_tabA[TABW];        // quantized u16-pair table, copy A
__device__ unsigned g_tabB[TABW];        // one-u16-shifted copy B
__device__ float g_A[NN];                // A[di*100+j1] = sum_j2 sqrt(di^2+(j1-j2)^2)
__device__ int   g_list[NN];             // (i2+99)*200 + (j2+99)
__device__ int   g_nlist;
__device__ float g_pT[NSLICE * 10240];
__device__ float g_pS[NSLICE * 10240];
__device__ float g_red[NB];
__device__ int   g_barA = 0, g_barB = 0, g_done = 0;

__device__ __forceinline__ void grid_barrier(int* ctr) {
    __syncthreads();
    if (threadIdx.x == 0) {
        atomicAdd(ctr, 1);
        while (*(volatile int*)ctr != NB) { }   // hot spin: wake within ~1 L2 read
    }
    __syncthreads();
}

__device__ __forceinline__ float sqrt_fast(float x) {
    float r; asm("sqrt.approx.f32 %0, %1;" : "=f"(r) : "f"(x)); return r;
}

// quantized distance at flat u16 index t of the 199x200 table
__device__ __forceinline__ unsigned qdist(int t) {
    int a = t / TW2;
    int c = t - a * TW2;
    int dx = a - 99, dy = c - 99;
    return __float2uint_rn(sqrt_fast((float)(dx * dx + dy * dy)) * QSCALE);
}

__global__ __launch_bounds__(NT, 1) void k_fused(const float* __restrict__ prob,
                                                 const float* __restrict__ gt,
                                                 float* __restrict__ out) {
    extern __shared__ unsigned char smraw[];
    unsigned* wA = (unsigned*)smraw;                 // u16-pair words, copy A
    unsigned* wB = (unsigned*)(smraw + DB);          // shifted copy B
    int* slist = (int*)(smraw + SLIST_OFF);

    const int bid = blockIdx.x;
    const int tid = threadIdx.x;
    const int warp = tid >> 5, lane = tid & 31;

    const int chunk = bid / NSLICE;
    const int s = bid - chunk * NSLICE;
    const int o0 = chunk * OUTB;
    const int i1lo = o0 / 100;
    int i1hi = (o0 + OUTB - 1) / 100; if (i1hi > 99) i1hi = 99;
    const int rlo = 99 - i1hi;
    const int nrows = 100 + (i1hi - i1lo);
    const int nW = nrows * 100;                      // u32 words per smem copy

    // ---------------- Phase A0 ----------------
    // Compaction block: issue ALL gt loads first (MLP=10) so the DRAM round
    // trip hides under the table/A-row work below.
    float v[10];
    if (bid == CPB) {
        #pragma unroll
        for (int it = 0; it < 10; ++it) {
            int o = (it * 32 + warp) * 32 + lane;
            v[it] = (o < NN) ? gt[o] : 0.0f;
        }
    }

    // Global quantized tables: 2*19900 words over 143360 threads -> 1 word max.
    {
        int idx = bid * NT + tid;
        if (idx < 2 * TABW) {
            if (idx < TABW) {
                int t0 = 2 * idx;
                g_tabA[idx] = qdist(t0) | (qdist(t0 + 1) << 16);
            } else {
                int w = idx - TABW;
                int t0 = 2 * w + 1;
                int t1 = (t0 + 1 < 2 * TABW) ? (t0 + 1) : t0;
                g_tabB[w] = qdist(t0) | (qdist(t1) << 16);
            }
        }
    }

    if (bid < 100) {
        // A-rows via prefix identity: A[di][j1] = r[0] + P[j1] + P[99-j1]
        __shared__ float sr[100];
        __shared__ float sp[100];
        if (tid < 100) {
            float fd2 = (float)(bid * bid);
            sr[tid] = sqrtf(fd2 + (float)(tid * tid));
        }
        __syncthreads();
        if (tid == 0) {
            float run = 0.f;
            sp[0] = 0.f;
            for (int d = 1; d < 100; ++d) { run += sr[d]; sp[d] = run; }
        }
        __syncthreads();
        if (tid < 100)
            g_A[bid * 100 + tid] = sr[0] + sp[tid] + sp[99 - tid];
    } else if (bid == CPB) {
        // deterministic parallel compaction of py = (gt >= 0.5), data in regs
        __shared__ unsigned sbal[320];
        __shared__ int soff[320];
        #pragma unroll
        for (int it = 0; it < 10; ++it) {
            int seg = it * 32 + warp;
            if (seg < NSEG) {
                int o = seg * 32 + lane;
                bool p = (o < NN) && (v[it] >= 0.5f);
                unsigned bal = __ballot_sync(0xffffffffu, p);
                if (lane == 0) sbal[seg] = bal;
            }
        }
        __syncthreads();
        if (warp == 0) {
            int base = 0;
            #pragma unroll
            for (int c = 0; c < 10; ++c) {
                int sg = c * 32 + lane;
                int cnt = (sg < NSEG) ? __popc(sbal[sg]) : 0;
                int incl = cnt;
                #pragma unroll
                for (int d = 1; d < 32; d <<= 1) {
                    int vv = __shfl_up_sync(0xffffffffu, incl, d);
                    if (lane >= d) incl += vv;
                }
                if (sg < NSEG) soff[sg] = base + incl - cnt;
                base += __shfl_sync(0xffffffffu, incl, 31);
            }
            if (lane == 0) g_nlist = base;
        }
        __syncthreads();
        #pragma unroll
        for (int it = 0; it < 10; ++it) {
            int seg = it * 32 + warp;
            if (seg < NSEG) {
                unsigned bal = sbal[seg];
                if ((bal >> lane) & 1u) {
                    int o = seg * 32 + lane;
                    int pre = __popc(bal & ((1u << lane) - 1u));
                    int i2 = o / 100, j2 = o - i2 * 100;
                    g_list[soff[seg] + pre] = (i2 + 99) * TW2 + (j2 + 99);
                }
            }
        }
    }

    __threadfence();
    grid_barrier(&g_barA);

    // ---------------- Phase A1: stage table window from L2 into smem ------
    {
        const int4* srcA = (const int4*)(g_tabA + rlo * 100);
        const int4* srcB = (const int4*)(g_tabB + rlo * 100);
        int4* dA = (int4*)wA;
        int4* dB = (int4*)wB;
        int nv = nW >> 2;
        for (int k2 = tid; k2 < nv; k2 += NT) {
            dA[k2] = srcA[k2];
            dB[k2] = srcB[k2];
        }
    }

    // ---------------- Phase B: main sparse accumulate ----------------
    int n = *(volatile int*)&g_nlist;
    int e0 = (s * n) / NSLICE;
    int e1 = ((s + 1) * n) / NSLICE;
    int cnt = e1 - e0;
    int badj = rlo * TW2 + 1;            // F = G - badj
    for (int k = tid; k < cnt; k += NT) {
        int F = g_list[e0 + k] - badj;
        int p = F & 1;
        slist[k] = 2 * (F - p) + p * DB;
    }
    __syncthreads();

    int oe = o0 + 2 * tid;               // even output; pair (oe, oe+1)
    bool valid = (oe < NN);
    int oc = valid ? oe : (NN - 2);
    int i1 = oc / 100;
    int j1 = oc - i1 * 100;              // even
    int qq = j1 >> 1;

    unsigned baseA;
    asm("{ .reg .u64 t; cvta.to.shared.u64 t, %1; cvt.u32.u64 %0, t; }"
        : "=r"(baseA) : "l"(smraw));
    unsigned tb = baseA - 400u * (unsigned)i1 - 4u * (unsigned)qq;

    unsigned aE0 = 0, aE1 = 0, aO0 = 0, aO1 = 0;
    int k = 0;
    int n8 = cnt & ~7;
    for (; k < n8; k += 8) {
        int4 ea = *(const int4*)(slist + k);
        int4 eb = *(const int4*)(slist + k + 4);
        unsigned w0, w1, w2, w3, w4, w5, w6, w7;
        asm("ld.shared.u32 %0,[%1];" : "=r"(w0) : "r"(tb + (unsigned)ea.x));
        asm("ld.shared.u32 %0,[%1];" : "=r"(w1) : "r"(tb + (unsigned)ea.y));
        asm("ld.shared.u32 %0,[%1];" : "=r"(w2) : "r"(tb + (unsigned)ea.z));
        asm("ld.shared.u32 %0,[%1];" : "=r"(w3) : "r"(tb + (unsigned)ea.w));
        asm("ld.shared.u32 %0,[%1];" : "=r"(w4) : "r"(tb + (unsigned)eb.x));
        asm("ld.shared.u32 %0,[%1];" : "=r"(w5) : "r"(tb + (unsigned)eb.y));
        asm("ld.shared.u32 %0,[%1];" : "=r"(w6) : "r"(tb + (unsigned)eb.z));
        asm("ld.shared.u32 %0,[%1];" : "=r"(w7) : "r"(tb + (unsigned)eb.w));
        aE0 = __dp2a_lo(w0, 0x0100u, aE0); aO0 = __dp2a_lo(w0, 0x0001u, aO0);
        aE1 = __dp2a_lo(w1, 0x0100u, aE1); aO1 = __dp2a_lo(w1, 0x0001u, aO1);
        aE0 = __dp2a_lo(w2, 0x0100u, aE0); aO0 = __dp2a_lo(w2, 0x0001u, aO0);
        aE1 = __dp2a_lo(w3, 0x0100u, aE1); aO1 = __dp2a_lo(w3, 0x0001u, aO1);
        aE0 = __dp2a_lo(w4, 0x0100u, aE0); aO0 = __dp2a_lo(w4, 0x0001u, aO0);
        aE1 = __dp2a_lo(w5, 0x0100u, aE1); aO1 = __dp2a_lo(w5, 0x0001u, aO1);
        aE0 = __dp2a_lo(w6, 0x0100u, aE0); aO0 = __dp2a_lo(w6, 0x0001u, aO0);
        aE1 = __dp2a_lo(w7, 0x0100u, aE1); aO1 = __dp2a_lo(w7, 0x0001u, aO1);
    }
    for (; k < cnt; ++k) {
        unsigned w0;
        asm("ld.shared.u32 %0,[%1];" : "=r"(w0) : "r"(tb + (unsigned)slist[k]));
        aE0 = __dp2a_lo(w0, 0x0100u, aE0);
        aO0 = __dp2a_lo(w0, 0x0001u, aO0);
    }
    float Te = __uint2float_rn(aE0 + aE1) * (1.0f / QSCALE);
    float To = __uint2float_rn(aO0 + aO1) * (1.0f / QSCALE);

    // slice partial of the (input-independent) rowsum S for both outputs
    int i2a = (100 * s) / NSLICE;
    int i2b = (100 * (s + 1)) / NSLICE;
    float sve = 0.f, svo = 0.f;
    const float2* A2 = (const float2*)g_A;
    for (int i2 = i2a; i2 < i2b; ++i2) {
        int di = i1 - i2; if (di < 0) di = -di;
        float2 vv = A2[di * 50 + qq];
        sve += vv.x; svo += vv.y;
    }

    if (valid) {
        *(float2*)&g_pT[s * 10240 + oe] = make_float2(Te, To);
        *(float2*)&g_pS[s * 10240 + oe] = make_float2(sve, svo);
    }
    __threadfence();
    grid_barrier(&g_barB);

    // ---------------- Phase C: distributed reduce (all 140 blocks) --------
    {
        __shared__ float wsum[4];
        float ls = 0.f;
        int o = bid * OPC + tid;          // threads 0..OPC-1 active
        if (tid < OPC && o < NN) {
            float T = 0.f, S = 0.f;
            #pragma unroll
            for (int q2 = 0; q2 < NSLICE; ++q2) {
                T += g_pT[q2 * 10240 + o];
                S += g_pS[q2 * 10240 + o];
            }
            float px = (prob[o] >= 0.5f) ? 1.0f : 0.0f;
            ls = fabsf(px * S - T);
        }
        if (warp < 3) {
            #pragma unroll
            for (int off = 16; off; off >>= 1)
                ls += __shfl_down_sync(0xffffffffu, ls, off);
            if (lane == 0) wsum[warp] = ls;
        }
        __syncthreads();
        if (tid == 0) {
            g_red[bid] = wsum[0] + wsum[1] + wsum[2];
            __threadfence();
            int fin = atomicAdd(&g_done, 1);
            if (fin == NB - 1) {          // last block: all g_red visible
                float tt = 0.f;
                const float4* r4 = (const float4*)g_red;
                #pragma unroll
                for (int b = 0; b < NB / 4; ++b) {
                    float4 rr = r4[b];
                    tt += ((rr.x + rr.y) + (rr.z + rr.w));
                }
                out[0] = tt * (1.0f / ((float)NN * (float)NN));
                // replay-safe counter reset (everyone else already finished)
                g_barA = 0; g_barB = 0; g_done = 0;
                __threadfence();
            }
        }
    }
}

extern "C" void kernel_launch(void* const* d_in, const int* in_sizes, int n_in,
                              void* d_out, int out_size) {
    const float* prob = (const float*)d_in[0];
    const float* gt   = (const float*)d_in[1];
    float* out = (float*)d_out;

    cudaFuncSetAttribute(k_fused, cudaFuncAttributeMaxDynamicSharedMemorySize, SMEM_BYTES);
    k_fused<<<NB, NT, SMEM_BYTES>>>(prob, gt, out);
}

// round 10
// speedup vs baseline: 1.1648x; 1.0426x over previous
#include <cuda_runtime.h>
#include <math.h>

#define NN 10000
#define NSLICE 28
#define NCHUNK 5
#define NB 140
#define NT 1024
#define OUTB 2048              // outputs per chunk (2 per thread)
#define MAXR 121               // max table rows any block needs
#define TW2 200                // u16 row width (even)
#define TABW (199 * 100)       // u32 words per global table copy = 19900
#define AWORDS (MAXR * 100)    // u32 words per smem copy = 12100
#define DB (AWORDS * 4)        // byte offset of smem copy B = 48400
#define SLIST_OFF (2 * DB)     // 96800, 16B aligned
#define SLIST_MAX 512
#define SMEM_BYTES (SLIST_OFF + SLIST_MAX * 4)
#define NSEG 313
#define QSCALE 448.0f
#define OPC 72                 // outputs per block in k3 (72*140 >= 10000)

__device__ unsigned g_tabA[TABW];        // quantized u16-pair table, copy A
__device__ unsigned g_tabB[TABW];        // one-u16-shifted copy B
__device__ float g_A[NN];                // A[di*100+j1] = sum_j2 sqrt(di^2+(j1-j2)^2)
__device__ int   g_list[NN];             // (i2+99)*200 + (j2+99)
__device__ int   g_nlist;
__device__ float g_pT[NSLICE * 10240];
__device__ float g_pS[NSLICE * 10240];
__device__ float g_red[NB];
__device__ int   g_done;

__device__ __forceinline__ float sqrt_fast(float x) {
    float r; asm("sqrt.approx.f32 %0, %1;" : "=f"(r) : "f"(x)); return r;
}

// quantized distance at flat u16 index t of the 199x200 table
__device__ __forceinline__ unsigned qdist(int t) {
    int a = t / TW2;
    int c = t - a * TW2;
    int dx = a - 99, dy = c - 99;
    return __float2uint_rn(sqrt_fast((float)(dx * dx + dy * dy)) * QSCALE);
}

// ---------------------------------------------------------------------------
// K1: global tables (distributed), A-rows (blocks 0..99), compaction (block
//     100), g_done reset. No cross-block deps inside the kernel.
// ---------------------------------------------------------------------------
__global__ __launch_bounds__(NT, 1) void k_prep(const float* __restrict__ gt) {
    const int bid = blockIdx.x;
    const int tid = threadIdx.x;
    const int warp = tid >> 5, lane = tid & 31;

    // compaction block: all gt loads first (MLP=10), ballots on registers
    float v[10];
    if (bid == 100) {
        #pragma unroll
        for (int it = 0; it < 10; ++it) {
            int o = (it * 32 + warp) * 32 + lane;
            v[it] = (o < NN) ? gt[o] : 0.0f;
        }
        if (tid == 0) g_done = 0;
    }

    // distributed global table gen: 2*19900 words over 143360 threads
    {
        int idx = bid * NT + tid;
        if (idx < 2 * TABW) {
            if (idx < TABW) {
                int t0 = 2 * idx;
                g_tabA[idx] = qdist(t0) | (qdist(t0 + 1) << 16);
            } else {
                int w = idx - TABW;
                int t0 = 2 * w + 1;
                int t1 = (t0 + 1 < 2 * TABW) ? (t0 + 1) : t0;
                g_tabB[w] = qdist(t0) | (qdist(t1) << 16);
            }
        }
    }

    if (bid < 100) {
        // A-rows via prefix identity: A[di][j1] = r[0] + P[j1] + P[99-j1]
        __shared__ float sr[100];
        __shared__ float sp[100];
        if (tid < 100) {
            float fd2 = (float)(bid * bid);
            sr[tid] = sqrtf(fd2 + (float)(tid * tid));
        }
        __syncthreads();
        if (tid == 0) {
            float run = 0.f;
            sp[0] = 0.f;
            for (int d = 1; d < 100; ++d) { run += sr[d]; sp[d] = run; }
        }
        __syncthreads();
        if (tid < 100)
            g_A[bid * 100 + tid] = sr[0] + sp[tid] + sp[99 - tid];
    } else if (bid == 100) {
        // deterministic parallel compaction of py = (gt >= 0.5)
        __shared__ unsigned sbal[320];
        __shared__ int soff[320];
        #pragma unroll
        for (int it = 0; it < 10; ++it) {
            int seg = it * 32 + warp;
            if (seg < NSEG) {
                int o = seg * 32 + lane;
                bool p = (o < NN) && (v[it] >= 0.5f);
                unsigned bal = __ballot_sync(0xffffffffu, p);
                if (lane == 0) sbal[seg] = bal;
            }
        }
        __syncthreads();
        if (warp == 0) {
            int base = 0;
            #pragma unroll
            for (int c = 0; c < 10; ++c) {
                int sg = c * 32 + lane;
                int cnt = (sg < NSEG) ? __popc(sbal[sg]) : 0;
                int incl = cnt;
                #pragma unroll
                for (int d = 1; d < 32; d <<= 1) {
                    int vv = __shfl_up_sync(0xffffffffu, incl, d);
                    if (lane >= d) incl += vv;
                }
                if (sg < NSEG) soff[sg] = base + incl - cnt;
                base += __shfl_sync(0xffffffffu, incl, 31);
            }
            if (lane == 0) g_nlist = base;
        }
        __syncthreads();
        #pragma unroll
        for (int it = 0; it < 10; ++it) {
            int seg = it * 32 + warp;
            if (seg < NSEG) {
                unsigned bal = sbal[seg];
                if ((bal >> lane) & 1u) {
                    int o = seg * 32 + lane;
                    int pre = __popc(bal & ((1u << lane) - 1u));
                    int i2 = o / 100, j2 = o - i2 * 100;
                    g_list[soff[seg] + pre] = (i2 + 99) * TW2 + (j2 + 99);
                }
            }
        }
    }
}

// ---------------------------------------------------------------------------
// K2: stage table window, sparse DP2A accumulate, S partials. No barriers.
// ---------------------------------------------------------------------------
__global__ __launch_bounds__(NT, 1) void k_main() {
    extern __shared__ unsigned char smraw[];
    unsigned* wA = (unsigned*)smraw;
    unsigned* wB = (unsigned*)(smraw + DB);
    int* slist = (int*)(smraw + SLIST_OFF);

    const int bid = blockIdx.x;
    const int tid = threadIdx.x;

    const int chunk = bid / NSLICE;
    const int s = bid - chunk * NSLICE;
    const int o0 = chunk * OUTB;
    int i1hi = (o0 + OUTB - 1) / 100; if (i1hi > 99) i1hi = 99;
    const int i1lo = o0 / 100;
    const int rlo = 99 - i1hi;
    const int nrows = 100 + (i1hi - i1lo);
    const int nW = nrows * 100;

    // stage table window from L2 into smem
    {
        const int4* srcA = (const int4*)(g_tabA + rlo * 100);
        const int4* srcB = (const int4*)(g_tabB + rlo * 100);
        int4* dA = (int4*)wA;
        int4* dB = (int4*)wB;
        int nv = nW >> 2;
        for (int k2 = tid; k2 < nv; k2 += NT) {
            dA[k2] = srcA[k2];
            dB[k2] = srcB[k2];
        }
    }

    int n = g_nlist;
    int e0 = (s * n) / NSLICE;
    int e1 = ((s + 1) * n) / NSLICE;
    int cnt = e1 - e0;
    int badj = rlo * TW2 + 1;
    for (int k = tid; k < cnt; k += NT) {
        int F = g_list[e0 + k] - badj;
        int p = F & 1;
        slist[k] = 2 * (F - p) + p * DB;
    }
    __syncthreads();

    int oe = o0 + 2 * tid;
    bool valid = (oe < NN);
    int oc = valid ? oe : (NN - 2);
    int i1 = oc / 100;
    int j1 = oc - i1 * 100;
    int qq = j1 >> 1;

    unsigned baseA;
    asm("{ .reg .u64 t; cvta.to.shared.u64 t, %1; cvt.u32.u64 %0, t; }"
        : "=r"(baseA) : "l"(smraw));
    unsigned tb = baseA - 400u * (unsigned)i1 - 4u * (unsigned)qq;

    unsigned aE0 = 0, aE1 = 0, aO0 = 0, aO1 = 0;
    int k = 0;
    int n8 = cnt & ~7;
    for (; k < n8; k += 8) {
        int4 ea = *(const int4*)(slist + k);
        int4 eb = *(const int4*)(slist + k + 4);
        unsigned w0, w1, w2, w3, w4, w5, w6, w7;
        asm("ld.shared.u32 %0,[%1];" : "=r"(w0) : "r"(tb + (unsigned)ea.x));
        asm("ld.shared.u32 %0,[%1];" : "=r"(w1) : "r"(tb + (unsigned)ea.y));
        asm("ld.shared.u32 %0,[%1];" : "=r"(w2) : "r"(tb + (unsigned)ea.z));
        asm("ld.shared.u32 %0,[%1];" : "=r"(w3) : "r"(tb + (unsigned)ea.w));
        asm("ld.shared.u32 %0,[%1];" : "=r"(w4) : "r"(tb + (unsigned)eb.x));
        asm("ld.shared.u32 %0,[%1];" : "=r"(w5) : "r"(tb + (unsigned)eb.y));
        asm("ld.shared.u32 %0,[%1];" : "=r"(w6) : "r"(tb + (unsigned)eb.z));
        asm("ld.shared.u32 %0,[%1];" : "=r"(w7) : "r"(tb + (unsigned)eb.w));
        aE0 = __dp2a_lo(w0, 0x0100u, aE0); aO0 = __dp2a_lo(w0, 0x0001u, aO0);
        aE1 = __dp2a_lo(w1, 0x0100u, aE1); aO1 = __dp2a_lo(w1, 0x0001u, aO1);
        aE0 = __dp2a_lo(w2, 0x0100u, aE0); aO0 = __dp2a_lo(w2, 0x0001u, aO0);
        aE1 = __dp2a_lo(w3, 0x0100u, aE1); aO1 = __dp2a_lo(w3, 0x0001u, aO1);
        aE0 = __dp2a_lo(w4, 0x0100u, aE0); aO0 = __dp2a_lo(w4, 0x0001u, aO0);
        aE1 = __dp2a_lo(w5, 0x0100u, aE1); aO1 = __dp2a_lo(w5, 0x0001u, aO1);
        aE0 = __dp2a_lo(w6, 0x0100u, aE0); aO0 = __dp2a_lo(w6, 0x0001u, aO0);
        aE1 = __dp2a_lo(w7, 0x0100u, aE1); aO1 = __dp2a_lo(w7, 0x0001u, aO1);
    }
    for (; k < cnt; ++k) {
        unsigned w0;
        asm("ld.shared.u32 %0,[%1];" : "=r"(w0) : "r"(tb + (unsigned)slist[k]));
        aE0 = __dp2a_lo(w0, 0x0100u, aE0);
        aO0 = __dp2a_lo(w0, 0x0001u, aO0);
    }
    float Te = __uint2float_rn(aE0 + aE1) * (1.0f / QSCALE);
    float To = __uint2float_rn(aO0 + aO1) * (1.0f / QSCALE);

    // slice partial of the (input-independent) rowsum S for both outputs
    int i2a = (100 * s) / NSLICE;
    int i2b = (100 * (s + 1)) / NSLICE;
    float sve = 0.f, svo = 0.f;
    const float2* A2 = (const float2*)g_A;
    for (int i2 = i2a; i2 < i2b; ++i2) {
        int di = i1 - i2; if (di < 0) di = -di;
        float2 vv = A2[di * 50 + qq];
        sve += vv.x; svo += vv.y;
    }

    if (valid) {
        *(float2*)&g_pT[s * 10240 + oe] = make_float2(Te, To);
        *(float2*)&g_pS[s * 10240 + oe] = make_float2(sve, svo);
    }
}

// ---------------------------------------------------------------------------
// K3: distributed reduce; last block writes the scalar.
// ---------------------------------------------------------------------------
__global__ void k_red(const float* __restrict__ prob, float* __restrict__ out) {
    __shared__ float wsum[4];
    const int bid = blockIdx.x;
    const int tid = threadIdx.x;
    const int warp = tid >> 5, lane = tid & 31;

    float ls = 0.f;
    int o = bid * OPC + tid;
    if (tid < OPC && o < NN) {
        float T = 0.f, S = 0.f;
        #pragma unroll
        for (int q2 = 0; q2 < NSLICE; ++q2) {
            T += g_pT[q2 * 10240 + o];
            S += g_pS[q2 * 10240 + o];
        }
        float px = (prob[o] >= 0.5f) ? 1.0f : 0.0f;
        ls = fabsf(px * S - T);
    }
    if (warp < 3) {
        #pragma unroll
        for (int off = 16; off; off >>= 1)
            ls += __shfl_down_sync(0xffffffffu, ls, off);
        if (lane == 0) wsum[warp] = ls;
    }
    __syncthreads();
    if (tid == 0) {
        g_red[bid] = wsum[0] + wsum[1] + wsum[2];
        __threadfence();
        int fin = atomicAdd(&g_done, 1);
        if (fin == NB - 1) {
            float tt = 0.f;
            const float4* r4 = (const float4*)g_red;
            #pragma unroll
            for (int b = 0; b < NB / 4; ++b) {
                float4 rr = r4[b];
                tt += ((rr.x + rr.y) + (rr.z + rr.w));
            }
            out[0] = tt * (1.0f / ((float)NN * (float)NN));
        }
    }
}

extern "C" void kernel_launch(void* const* d_in, const int* in_sizes, int n_in,
                              void* d_out, int out_size) {
    const float* prob = (const float*)d_in[0];
    const float* gt   = (const float*)d_in[1];
    float* out = (float*)d_out;

    cudaFuncSetAttribute(k_main, cudaFuncAttributeMaxDynamicSharedMemorySize, SMEM_BYTES);
    k_prep<<<NB, NT>>>(gt);
    k_main<<<NB, NT, SMEM_BYTES>>>();
    k_red<<<NB, 128>>>(prob, out);
}

// round 11
// speedup vs baseline: 1.2888x; 1.1064x over previous
#include <cuda_runtime.h>
#include <math.h>

#define NN 10000
#define NSLICE 28
#define NB 140
#define NT 1024
#define OUTB 2048              // outputs per chunk (2 per thread)
#define MAXR 121               // max table rows any block needs
#define TW2 200                // u16 row width (even)
#define TABW (199 * 100)       // u32 words per global table copy = 19900
#define AWORDS (MAXR * 100)    // u32 words per smem copy = 12100
#define DB (AWORDS * 4)        // byte offset of smem copy B = 48400
#define SLIST_OFF (2 * DB)     // 96800, 16B aligned
#define SLIST_MAX 512
#define SMEM_BYTES (SLIST_OFF + SLIST_MAX * 4)
#define QSCALE 448.0f
#define OPC 72                 // outputs per block in k3 (72*140 >= 10000)

__device__ unsigned g_tabA[TABW];        // quantized u16-pair table, copy A
__device__ unsigned g_tabB[TABW];        // one-u16-shifted copy B
__device__ float g_A[NN];                // A[di*100+j1] = sum_j2 sqrt(di^2+(j1-j2)^2)
__device__ int   g_list[NN];             // (i2+99)*200 + (j2+99)
__device__ int   g_nlist;
__device__ float g_pT[NSLICE * 10240];
__device__ float g_pS[NSLICE * 10240];
__device__ float g_red[NB];
__device__ int   g_done;

__device__ __forceinline__ float sqrt_fast(float x) {
    float r; asm("sqrt.approx.f32 %0, %1;" : "=f"(r) : "f"(x)); return r;
}

// quantized distance at flat u16 index t of the 199x200 table
__device__ __forceinline__ unsigned qdist(int t) {
    int a = t / TW2;
    int c = t - a * TW2;
    int dx = a - 99, dy = c - 99;
    return __float2uint_rn(sqrt_fast((float)(dx * dx + dy * dy)) * QSCALE);
}

// ---------------------------------------------------------------------------
// K1: global tables (distributed), A-rows (blocks 0..99), compaction (block
//     100), g_done reset. All serial scans replaced with parallel ones.
// ---------------------------------------------------------------------------
__global__ __launch_bounds__(NT, 1) void k_prep(const float* __restrict__ gt) {
    const int bid = blockIdx.x;
    const int tid = threadIdx.x;
    const int warp = tid >> 5, lane = tid & 31;

    // compaction block: prefetch all 10 gt values (MLP=10) BEFORE any ballot
    float vv[10];
    const int o_base = warp * 320 + lane;    // warp owns elements [320w, 320w+320)
    if (bid == 100) {
        #pragma unroll
        for (int it = 0; it < 10; ++it) {
            int o = o_base + it * 32;
            vv[it] = (o < NN) ? gt[o] : 0.0f;
        }
        if (tid == 0) g_done = 0;
    }

    // distributed global table gen: 2*19900 words over 143360 threads
    {
        int idx = bid * NT + tid;
        if (idx < 2 * TABW) {
            if (idx < TABW) {
                int t0 = 2 * idx;
                g_tabA[idx] = qdist(t0) | (qdist(t0 + 1) << 16);
            } else {
                int w = idx - TABW;
                int t0 = 2 * w + 1;
                int t1 = (t0 + 1 < 2 * TABW) ? (t0 + 1) : t0;
                g_tabB[w] = qdist(t0) | (qdist(t1) << 16);
            }
        }
    }

    if (bid < 100) {
        // A-rows: A[di][j1] = r[0] + P[j1] + P[99-j1], P = prefix of r[1..99].
        // Parallel scan: 4 warps shfl-scan, combine via 4-word shared.
        __shared__ float sr[100];
        __shared__ float sp[100];
        __shared__ float wtot[4];
        if (tid < 100)
            sr[tid] = sqrtf((float)(bid * bid + tid * tid));
        __syncthreads();
        float x = 0.f;
        if (tid < 128) {
            x = (tid >= 1 && tid < 100) ? sr[tid] : 0.f;
            #pragma unroll
            for (int d = 1; d < 32; d <<= 1) {
                float v = __shfl_up_sync(0xffffffffu, x, d);
                if (lane >= d) x += v;
            }
            if (lane == 31) wtot[warp] = x;
        }
        __syncthreads();
        if (tid < 100) {
            float add = 0.f;
            #pragma unroll
            for (int w2 = 0; w2 < 3; ++w2)
                if (w2 < warp) add += wtot[w2];
            sp[tid] = x + add;
        }
        __syncthreads();
        if (tid < 100)
            g_A[bid * 100 + tid] = sr[0] + sp[tid] + sp[99 - tid];
    } else if (bid == 100) {
        // fully parallel deterministic compaction of py = (gt >= 0.5)
        __shared__ int swtot[32];
        __shared__ int swoff[32];
        unsigned bal[10];
        #pragma unroll
        for (int it = 0; it < 10; ++it) {
            int o = o_base + it * 32;
            bool p = (o < NN) && (vv[it] >= 0.5f);
            bal[it] = __ballot_sync(0xffffffffu, p);
        }
        // warp-local exclusive prefix over its 10 segment counts (registers)
        int pre[10]; int run = 0;
        #pragma unroll
        for (int it = 0; it < 10; ++it) { pre[it] = run; run += __popc(bal[it]); }
        if (lane == 0) swtot[warp] = run;
        __syncthreads();
        if (warp == 0) {
            int t = swtot[lane];
            int incl = t;
            #pragma unroll
            for (int d = 1; d < 32; d <<= 1) {
                int v = __shfl_up_sync(0xffffffffu, incl, d);
                if (lane >= d) incl += v;
            }
            swoff[lane] = incl - t;
            if (lane == 31) g_nlist = incl;
        }
        __syncthreads();
        int base = swoff[warp];
        #pragma unroll
        for (int it = 0; it < 10; ++it) {
            unsigned b = bal[it];
            if ((b >> lane) & 1u) {
                int o = o_base + it * 32;
                int pos = base + pre[it] + __popc(b & ((1u << lane) - 1u));
                int i2 = o / 100, j2 = o - i2 * 100;
                g_list[pos] = (i2 + 99) * TW2 + (j2 + 99);
            }
        }
    }
}

// ---------------------------------------------------------------------------
// K2: stage table window, sparse DP2A accumulate, S partials.
// ---------------------------------------------------------------------------
__global__ __launch_bounds__(NT, 1) void k_main() {
    extern __shared__ unsigned char smraw[];
    unsigned* wA = (unsigned*)smraw;
    unsigned* wB = (unsigned*)(smraw + DB);
    int* slist = (int*)(smraw + SLIST_OFF);

    const int bid = blockIdx.x;
    const int tid = threadIdx.x;

    const int chunk = bid / NSLICE;
    const int s = bid - chunk * NSLICE;
    const int o0 = chunk * OUTB;
    int i1hi = (o0 + OUTB - 1) / 100; if (i1hi > 99) i1hi = 99;
    const int i1lo = o0 / 100;
    const int rlo = 99 - i1hi;
    const int nrows = 100 + (i1hi - i1lo);
    const int nW = nrows * 100;

    // stage table window from L2 into smem
    {
        const int4* srcA = (const int4*)(g_tabA + rlo * 100);
        const int4* srcB = (const int4*)(g_tabB + rlo * 100);
        int4* dA = (int4*)wA;
        int4* dB = (int4*)wB;
        int nv = nW >> 2;
        for (int k2 = tid; k2 < nv; k2 += NT) {
            dA[k2] = srcA[k2];
            dB[k2] = srcB[k2];
        }
    }

    int n = g_nlist;
    int e0 = (s * n) / NSLICE;
    int e1 = ((s + 1) * n) / NSLICE;
    int cnt = e1 - e0;
    int badj = rlo * TW2 + 1;
    for (int k = tid; k < cnt; k += NT) {
        int F = g_list[e0 + k] - badj;
        int p = F & 1;
        slist[k] = 2 * (F - p) + p * DB;
    }
    __syncthreads();

    int oe = o0 + 2 * tid;
    bool valid = (oe < NN);
    int oc = valid ? oe : (NN - 2);
    int i1 = oc / 100;
    int j1 = oc - i1 * 100;
    int qq = j1 >> 1;

    unsigned baseA;
    asm("{ .reg .u64 t; cvta.to.shared.u64 t, %1; cvt.u32.u64 %0, t; }"
        : "=r"(baseA) : "l"(smraw));
    unsigned tb = baseA - 400u * (unsigned)i1 - 4u * (unsigned)qq;

    unsigned aE0 = 0, aE1 = 0, aO0 = 0, aO1 = 0;
    int k = 0;
    int n8 = cnt & ~7;
    for (; k < n8; k += 8) {
        int4 ea = *(const int4*)(slist + k);
        int4 eb = *(const int4*)(slist + k + 4);
        unsigned w0, w1, w2, w3, w4, w5, w6, w7;
        asm("ld.shared.u32 %0,[%1];" : "=r"(w0) : "r"(tb + (unsigned)ea.x));
        asm("ld.shared.u32 %0,[%1];" : "=r"(w1) : "r"(tb + (unsigned)ea.y));
        asm("ld.shared.u32 %0,[%1];" : "=r"(w2) : "r"(tb + (unsigned)ea.z));
        asm("ld.shared.u32 %0,[%1];" : "=r"(w3) : "r"(tb + (unsigned)ea.w));
        asm("ld.shared.u32 %0,[%1];" : "=r"(w4) : "r"(tb + (unsigned)eb.x));
        asm("ld.shared.u32 %0,[%1];" : "=r"(w5) : "r"(tb + (unsigned)eb.y));
        asm("ld.shared.u32 %0,[%1];" : "=r"(w6) : "r"(tb + (unsigned)eb.z));
        asm("ld.shared.u32 %0,[%1];" : "=r"(w7) : "r"(tb + (unsigned)eb.w));
        aE0 = __dp2a_lo(w0, 0x0100u, aE0); aO0 = __dp2a_lo(w0, 0x0001u, aO0);
        aE1 = __dp2a_lo(w1, 0x0100u, aE1); aO1 = __dp2a_lo(w1, 0x0001u, aO1);
        aE0 = __dp2a_lo(w2, 0x0100u, aE0); aO0 = __dp2a_lo(w2, 0x0001u, aO0);
        aE1 = __dp2a_lo(w3, 0x0100u, aE1); aO1 = __dp2a_lo(w3, 0x0001u, aO1);
        aE0 = __dp2a_lo(w4, 0x0100u, aE0); aO0 = __dp2a_lo(w4, 0x0001u, aO0);
        aE1 = __dp2a_lo(w5, 0x0100u, aE1); aO1 = __dp2a_lo(w5, 0x0001u, aO1);
        aE0 = __dp2a_lo(w6, 0x0100u, aE0); aO0 = __dp2a_lo(w6, 0x0001u, aO0);
        aE1 = __dp2a_lo(w7, 0x0100u, aE1); aO1 = __dp2a_lo(w7, 0x0001u, aO1);
    }
    for (; k < cnt; ++k) {
        unsigned w0;
        asm("ld.shared.u32 %0,[%1];" : "=r"(w0) : "r"(tb + (unsigned)slist[k]));
        aE0 = __dp2a_lo(w0, 0x0100u, aE0);
        aO0 = __dp2a_lo(w0, 0x0001u, aO0);
    }
    float Te = __uint2float_rn(aE0 + aE1) * (1.0f / QSCALE);
    float To = __uint2float_rn(aO0 + aO1) * (1.0f / QSCALE);

    // slice partial of the (input-independent) rowsum S for both outputs
    int i2a = (100 * s) / NSLICE;
    int i2b = (100 * (s + 1)) / NSLICE;
    float sve = 0.f, svo = 0.f;
    const float2* A2 = (const float2*)g_A;
    for (int i2 = i2a; i2 < i2b; ++i2) {
        int di = i1 - i2; if (di < 0) di = -di;
        float2 av = A2[di * 50 + qq];
        sve += av.x; svo += av.y;
    }

    if (valid) {
        *(float2*)&g_pT[s * 10240 + oe] = make_float2(Te, To);
        *(float2*)&g_pS[s * 10240 + oe] = make_float2(sve, svo);
    }
}

// ---------------------------------------------------------------------------
// K3: distributed reduce; last block writes the scalar.
// ---------------------------------------------------------------------------
__global__ void k_red(const float* __restrict__ prob, float* __restrict__ out) {
    __shared__ float wsum[4];
    const int bid = blockIdx.x;
    const int tid = threadIdx.x;
    const int warp = tid >> 5, lane = tid & 31;

    float ls = 0.f;
    int o = bid * OPC + tid;
    if (tid < OPC && o < NN) {
        float T = 0.f, S = 0.f;
        #pragma unroll
        for (int q2 = 0; q2 < NSLICE; ++q2) {
            T += g_pT[q2 * 10240 + o];
            S += g_pS[q2 * 10240 + o];
        }
        float px = (prob[o] >= 0.5f) ? 1.0f : 0.0f;
        ls = fabsf(px * S - T);
    }
    if (warp < 3) {
        #pragma unroll
        for (int off = 16; off; off >>= 1)
            ls += __shfl_down_sync(0xffffffffu, ls, off);
        if (lane == 0) wsum[warp] = ls;
    }
    __syncthreads();
    if (tid == 0) {
        g_red[bid] = wsum[0] + wsum[1] + wsum[2];
        __threadfence();
        int fin = atomicAdd(&g_done, 1);
        if (fin == NB - 1) {
            float tt = 0.f;
            const float4* r4 = (const float4*)g_red;
            #pragma unroll
            for (int b = 0; b < NB / 4; ++b) {
                float4 rr = r4[b];
                tt += ((rr.x + rr.y) + (rr.z + rr.w));
            }
            out[0] = tt * (1.0f / ((float)NN * (float)NN));
        }
    }
}

extern "C" void kernel_launch(void* const* d_in, const int* in_sizes, int n_in,
                              void* d_out, int out_size) {
    const float* prob = (const float*)d_in[0];
    const float* gt   = (const float*)d_in[1];
    float* out = (float*)d_out;

    cudaFuncSetAttribute(k_main, cudaFuncAttributeMaxDynamicSharedMemorySize, SMEM_BYTES);
    k_prep<<<NB, NT>>>(gt);
    k_main<<<NB, NT, SMEM_BYTES>>>();
    k_red<<<NB, 128>>>(prob, out);
}

// round 12
// speedup vs baseline: 1.2947x; 1.0046x over previous
#include <cuda_runtime.h>
#include <math.h>

#define NN 10000
#define NSLICE 28
#define NB 140
#define NT 1024
#define OUTB 2048              // outputs per chunk (2 per thread)
#define MAXR 121               // max table rows any block needs
#define TW2 200                // u16 row width (even)
#define TABW (199 * 100)       // u32 words per global table copy = 19900
#define AWORDS (MAXR * 100)    // u32 words per smem copy = 12100
#define DB (AWORDS * 4)        // byte offset of smem copy B = 48400
#define SLIST_OFF (2 * DB)     // 96800, 16B aligned
#define SLIST_MAX 512
#define SMEM_BYTES (SLIST_OFF + SLIST_MAX * 4)
#define QSCALE 448.0f
#define OPC 72                 // outputs per block in k3 (72*140 >= 10000)
#define K1B 16                 // tiny k_prep grid

__device__ unsigned g_tabA[TABW];        // quantized u16-pair table, copy A
__device__ unsigned g_tabB[TABW];        // one-u16-shifted copy B
__device__ float g_A[NN];                // A[di*100+j1] = sum_j2 sqrt(di^2+(j1-j2)^2)
__device__ int   g_list[NN];             // (i2+99)*200 + (j2+99)
__device__ int   g_nlist;
__device__ float g_pT[NSLICE * 10240];
__device__ float g_pS[NSLICE * 10240];
__device__ float g_red[NB];
__device__ int   g_done;

__device__ __forceinline__ float sqrt_fast(float x) {
    float r; asm("sqrt.approx.f32 %0, %1;" : "=f"(r) : "f"(x)); return r;
}

// quantized distance at flat u16 index t of the 199x200 table
__device__ __forceinline__ unsigned qdist(int t) {
    int a = t / TW2;
    int c = t - a * TW2;
    int dx = a - 99, dy = c - 99;
    return __float2uint_rn(sqrt_fast((float)(dx * dx + dy * dy)) * QSCALE);
}

__device__ __forceinline__ float wscan(float x, int lane) {
    #pragma unroll
    for (int d = 1; d < 32; d <<= 1) {
        float v = __shfl_up_sync(0xffffffffu, x, d);
        if (lane >= d) x += v;
    }
    return x;
}

// ---------------------------------------------------------------------------
// K1 (16 blocks): bid0 = compaction + g_done reset; bid1-4 = A-rows (25 rows
// each, one warp per row); bid5-15 = grid-stride table gen.
// ---------------------------------------------------------------------------
__global__ __launch_bounds__(NT, 1) void k_prep(const float* __restrict__ gt) {
    const int bid = blockIdx.x;
    const int tid = threadIdx.x;
    const int warp = tid >> 5, lane = tid & 31;

    if (bid == 0) {
        // fully parallel deterministic compaction of py = (gt >= 0.5)
        __shared__ int swtot[32];
        __shared__ int swoff[32];
        float vv[10];
        const int o_base = warp * 320 + lane;   // warp owns [320w, 320w+320)
        #pragma unroll
        for (int it = 0; it < 10; ++it) {
            int o = o_base + it * 32;
            vv[it] = (o < NN) ? gt[o] : 0.0f;
        }
        if (tid == 0) g_done = 0;
        unsigned bal[10];
        #pragma unroll
        for (int it = 0; it < 10; ++it) {
            int o = o_base + it * 32;
            bool p = (o < NN) && (vv[it] >= 0.5f);
            bal[it] = __ballot_sync(0xffffffffu, p);
        }
        int pre[10]; int run = 0;
        #pragma unroll
        for (int it = 0; it < 10; ++it) { pre[it] = run; run += __popc(bal[it]); }
        if (lane == 0) swtot[warp] = run;
        __syncthreads();
        if (warp == 0) {
            int t = swtot[lane];
            int incl = t;
            #pragma unroll
            for (int d = 1; d < 32; d <<= 1) {
                int v = __shfl_up_sync(0xffffffffu, incl, d);
                if (lane >= d) incl += v;
            }
            swoff[lane] = incl - t;
            if (lane == 31) g_nlist = incl;
        }
        __syncthreads();
        int base = swoff[warp];
        #pragma unroll
        for (int it = 0; it < 10; ++it) {
            unsigned b = bal[it];
            if ((b >> lane) & 1u) {
                int o = o_base + it * 32;
                int pos = base + pre[it] + __popc(b & ((1u << lane) - 1u));
                int i2 = o / 100, j2 = o - i2 * 100;
                g_list[pos] = (i2 + 99) * TW2 + (j2 + 99);
            }
        }
    } else if (bid <= 4) {
        // A-rows: one warp per row, 25 rows per block.
        // A[di][j1] = di + P[j1] + P[99-j1], P = inclusive prefix of r[1..99].
        __shared__ float sp[25 * 100];
        if (warp < 25) {
            int di = (bid - 1) * 25 + warp;
            float fd2 = (float)(di * di);
            int d0 = lane, d1 = lane + 32, d2 = lane + 64, d3 = lane + 96;
            float v0 = sqrtf(fd2 + (float)(d0 * d0));
            float v1 = sqrtf(fd2 + (float)(d1 * d1));
            float v2 = sqrtf(fd2 + (float)(d2 * d2));
            float v3 = (d3 < 100) ? sqrtf(fd2 + (float)(d3 * d3)) : 0.f;
            float s0 = wscan((d0 >= 1) ? v0 : 0.f, lane);
            float t0 = __shfl_sync(0xffffffffu, s0, 31);
            float s1 = wscan(v1, lane);
            float t1 = t0 + __shfl_sync(0xffffffffu, s1, 31);
            float s2 = wscan(v2, lane);
            float t2 = t1 + __shfl_sync(0xffffffffu, s2, 31);
            float s3 = wscan(v3, lane);
            float* row = sp + warp * 100;
            row[d0] = s0;
            row[d1] = s1 + t0;
            row[d2] = s2 + t1;
            if (d3 < 100) row[d3] = s3 + t2;
            __syncwarp();
            float fdi = (float)di;
            g_A[di * 100 + d0] = fdi + row[d0] + row[99 - d0];
            g_A[di * 100 + d1] = fdi + row[d1] + row[99 - d1];
            g_A[di * 100 + d2] = fdi + row[d2] + row[99 - d2];
            if (d3 < 100) g_A[di * 100 + d3] = fdi + row[d3] + row[99 - d3];
        }
    } else {
        // table gen: 2*19900 words over 11 blocks, grid-stride
        for (int idx = (bid - 5) * NT + tid; idx < 2 * TABW; idx += 11 * NT) {
            if (idx < TABW) {
                int t0 = 2 * idx;
                g_tabA[idx] = qdist(t0) | (qdist(t0 + 1) << 16);
            } else {
                int w = idx - TABW;
                int t0 = 2 * w + 1;
                int t1 = (t0 + 1 < 2 * TABW) ? (t0 + 1) : t0;
                g_tabB[w] = qdist(t0) | (qdist(t1) << 16);
            }
        }
    }
}

// ---------------------------------------------------------------------------
// K2: stage table window, sparse DP2A accumulate, S partials.
// ---------------------------------------------------------------------------
__global__ __launch_bounds__(NT, 1) void k_main() {
    extern __shared__ unsigned char smraw[];
    unsigned* wA = (unsigned*)smraw;
    unsigned* wB = (unsigned*)(smraw + DB);
    int* slist = (int*)(smraw + SLIST_OFF);

    const int bid = blockIdx.x;
    const int tid = threadIdx.x;

    const int chunk = bid / NSLICE;
    const int s = bid - chunk * NSLICE;
    const int o0 = chunk * OUTB;
    int i1hi = (o0 + OUTB - 1) / 100; if (i1hi > 99) i1hi = 99;
    const int i1lo = o0 / 100;
    const int rlo = 99 - i1hi;
    const int nrows = 100 + (i1hi - i1lo);
    const int nW = nrows * 100;

    // stage table window from L2 into smem
    {
        const int4* srcA = (const int4*)(g_tabA + rlo * 100);
        const int4* srcB = (const int4*)(g_tabB + rlo * 100);
        int4* dA = (int4*)wA;
        int4* dB = (int4*)wB;
        int nv = nW >> 2;
        for (int k2 = tid; k2 < nv; k2 += NT) {
            dA[k2] = srcA[k2];
            dB[k2] = srcB[k2];
        }
    }

    int n = g_nlist;
    int e0 = (s * n) / NSLICE;
    int e1 = ((s + 1) * n) / NSLICE;
    int cnt = e1 - e0;
    int badj = rlo * TW2 + 1;
    for (int k = tid; k < cnt; k += NT) {
        int F = g_list[e0 + k] - badj;
        int p = F & 1;
        slist[k] = 2 * (F - p) + p * DB;
    }
    __syncthreads();

    int oe = o0 + 2 * tid;
    bool valid = (oe < NN);
    int oc = valid ? oe : (NN - 2);
    int i1 = oc / 100;
    int j1 = oc - i1 * 100;
    int qq = j1 >> 1;

    unsigned baseA;
    asm("{ .reg .u64 t; cvta.to.shared.u64 t, %1; cvt.u32.u64 %0, t; }"
        : "=r"(baseA) : "l"(smraw));
    unsigned tb = baseA - 400u * (unsigned)i1 - 4u * (unsigned)qq;

    unsigned aE0 = 0, aE1 = 0, aO0 = 0, aO1 = 0;
    int k = 0;
    int n8 = cnt & ~7;
    for (; k < n8; k += 8) {
        int4 ea = *(const int4*)(slist + k);
        int4 eb = *(const int4*)(slist + k + 4);
        unsigned w0, w1, w2, w3, w4, w5, w6, w7;
        asm("ld.shared.u32 %0,[%1];" : "=r"(w0) : "r"(tb + (unsigned)ea.x));
        asm("ld.shared.u32 %0,[%1];" : "=r"(w1) : "r"(tb + (unsigned)ea.y));
        asm("ld.shared.u32 %0,[%1];" : "=r"(w2) : "r"(tb + (unsigned)ea.z));
        asm("ld.shared.u32 %0,[%1];" : "=r"(w3) : "r"(tb + (unsigned)ea.w));
        asm("ld.shared.u32 %0,[%1];" : "=r"(w4) : "r"(tb + (unsigned)eb.x));
        asm("ld.shared.u32 %0,[%1];" : "=r"(w5) : "r"(tb + (unsigned)eb.y));
        asm("ld.shared.u32 %0,[%1];" : "=r"(w6) : "r"(tb + (unsigned)eb.z));
        asm("ld.shared.u32 %0,[%1];" : "=r"(w7) : "r"(tb + (unsigned)eb.w));
        aE0 = __dp2a_lo(w0, 0x0100u, aE0); aO0 = __dp2a_lo(w0, 0x0001u, aO0);
        aE1 = __dp2a_lo(w1, 0x0100u, aE1); aO1 = __dp2a_lo(w1, 0x0001u, aO1);
        aE0 = __dp2a_lo(w2, 0x0100u, aE0); aO0 = __dp2a_lo(w2, 0x0001u, aO0);
        aE1 = __dp2a_lo(w3, 0x0100u, aE1); aO1 = __dp2a_lo(w3, 0x0001u, aO1);
        aE0 = __dp2a_lo(w4, 0x0100u, aE0); aO0 = __dp2a_lo(w4, 0x0001u, aO0);
        aE1 = __dp2a_lo(w5, 0x0100u, aE1); aO1 = __dp2a_lo(w5, 0x0001u, aO1);
        aE0 = __dp2a_lo(w6, 0x0100u, aE0); aO0 = __dp2a_lo(w6, 0x0001u, aO0);
        aE1 = __dp2a_lo(w7, 0x0100u, aE1); aO1 = __dp2a_lo(w7, 0x0001u, aO1);
    }
    for (; k < cnt; ++k) {
        unsigned w0;
        asm("ld.shared.u32 %0,[%1];" : "=r"(w0) : "r"(tb + (unsigned)slist[k]));
        aE0 = __dp2a_lo(w0, 0x0100u, aE0);
        aO0 = __dp2a_lo(w0, 0x0001u, aO0);
    }
    float Te = __uint2float_rn(aE0 + aE1) * (1.0f / QSCALE);
    float To = __uint2float_rn(aO0 + aO1) * (1.0f / QSCALE);

    // slice partial of the (input-independent) rowsum S for both outputs
    int i2a = (100 * s) / NSLICE;
    int i2b = (100 * (s + 1)) / NSLICE;
    float sve = 0.f, svo = 0.f;
    const float2* A2 = (const float2*)g_A;
    for (int i2 = i2a; i2 < i2b; ++i2) {
        int di = i1 - i2; if (di < 0) di = -di;
        float2 av = A2[di * 50 + qq];
        sve += av.x; svo += av.y;
    }

    if (valid) {
        *(float2*)&g_pT[s * 10240 + oe] = make_float2(Te, To);
        *(float2*)&g_pS[s * 10240 + oe] = make_float2(sve, svo);
    }
}

// ---------------------------------------------------------------------------
// K3: distributed reduce; last block writes the scalar.
// ---------------------------------------------------------------------------
__global__ void k_red(const float* __restrict__ prob, float* __restrict__ out) {
    __shared__ float wsum[4];
    const int bid = blockIdx.x;
    const int tid = threadIdx.x;
    const int warp = tid >> 5, lane = tid & 31;

    float ls = 0.f;
    int o = bid * OPC + tid;
    if (tid < OPC && o < NN) {
        float T = 0.f, S = 0.f;
        #pragma unroll
        for (int q2 = 0; q2 < NSLICE; ++q2) {
            T += g_pT[q2 * 10240 + o];
            S += g_pS[q2 * 10240 + o];
        }
        float px = (prob[o] >= 0.5f) ? 1.0f : 0.0f;
        ls = fabsf(px * S - T);
    }
    if (warp < 3) {
        #pragma unroll
        for (int off = 16; off; off >>= 1)
            ls += __shfl_down_sync(0xffffffffu, ls, off);
        if (lane == 0) wsum[warp] = ls;
    }
    __syncthreads();
    if (tid == 0) {
        g_red[bid] = wsum[0] + wsum[1] + wsum[2];
        __threadfence();
        int fin = atomicAdd(&g_done, 1);
        if (fin == NB - 1) {
            float tt = 0.f;
            const float4* r4 = (const float4*)g_red;
            #pragma unroll
            for (int b = 0; b < NB / 4; ++b) {
                float4 rr = r4[b];
                tt += ((rr.x + rr.y) + (rr.z + rr.w));
            }
            out[0] = tt * (1.0f / ((float)NN * (float)NN));
        }
    }
}

extern "C" void kernel_launch(void* const* d_in, const int* in_sizes, int n_in,
                              void* d_out, int out_size) {
    const float* prob = (const float*)d_in[0];
    const float* gt   = (const float*)d_in[1];
    float* out = (float*)d_out;

    cudaFuncSetAttribute(k_main, cudaFuncAttributeMaxDynamicSharedMemorySize, SMEM_BYTES);
    k_prep<<<K1B, NT>>>(gt);
    k_main<<<NB, NT, SMEM_BYTES>>>();
    k_red<<<NB, 128>>>(prob, out);
}